// round 11
// baseline (speedup 1.0000x reference)
#include <cuda_runtime.h>

// PowerSpectrum, R11:
//  - diagonal-pairing FFMA2: acc d[rp]={G[2rp][b],G[2rp+1][b+1]},
//    a[rp]={G[2rp][b+1],G[2rp+1][b]}; both A and B operands are native u64
//    register pairs; only a swapped B (2 MOVs) needed per k (was 4 dup MOVs)
//  - diag(G) stores folded into the slab epilogue (b==a lanes scale by
//    1/sqrt2); the separate diag phase is deleted
//
// Per env j: for l = 0..6, G_l = S_l S_l^T / sqrt(2l+1), S_l: [64, 2l+1].
// features = concat_l [ diag(G_l) (64) ; sqrt(2)*triu(G_l,1) (2016) ] (14560)
// out = features / max(||features||, 1e-12)

#define NJ       8192
#define NA       64
#define NL       7
#define FEAT_L   2080
#define NDIM     14560
#define NTHREADS 256
#define STRIDE   68               // k-row stride in floats
#define S_FLOATS 3332             // 49 * 68
#define SMEM_BYTES (S_FLOATS * 4) // 13328
#define NWTASK   35               // 7 l * 5 packed 8-row slab tasks

typedef unsigned long long u64;

__device__ __forceinline__ u64 swap2(u64 v) {
    u64 r;
    asm("{\n\t.reg .f32 lo, hi;\n\t"
        "mov.b64 {lo, hi}, %1;\n\t"
        "mov.b64 %0, {hi, lo};\n\t}"
        : "=l"(r) : "l"(v));
    return r;
}
__device__ __forceinline__ void ffma2(u64& d, u64 a, u64 b) {
    asm("fma.rn.f32x2 %0, %1, %2, %0;" : "+l"(d) : "l"(a), "l"(b));
}
__device__ __forceinline__ void mul2(u64& d, u64 s) {
    asm("mul.rn.f32x2 %0, %0, %1;" : "+l"(d) : "l"(s));
}
__device__ __forceinline__ u64 dup2(float x) {
    u64 r;
    asm("mov.b64 %0, {%1, %1};" : "=l"(r) : "f"(x));
    return r;
}
__device__ __forceinline__ float2 unpack2(u64 v) {
    float lo, hi;
    asm("mov.b64 {%0, %1}, %2;" : "=f"(lo), "=f"(hi) : "l"(v));
    return make_float2(lo, hi);
}

// d[rp] = {G[2rp][b], G[2rp+1][b+1]},  a[rp] = {G[2rp][b+1], G[2rp+1][b]}
template<int K>
__device__ __forceinline__ void slab_gram8(const float* __restrict__ rowA,
                                           const float* __restrict__ rowB,
                                           u64* d, u64* an)
{
    #pragma unroll
    for (int k = 0; k < K; ++k) {
        ulonglong2 A0 = *(const ulonglong2*)(rowA + k * STRIDE);     // rows 0-3
        ulonglong2 A1 = *(const ulonglong2*)(rowA + k * STRIDE + 4); // rows 4-7
        u64 Bn = *(const u64*)(rowB + k * STRIDE);                   // {b, b+1}
        u64 Bs = swap2(Bn);                                          // {b+1, b}
        ffma2(d[0], A0.x, Bn); ffma2(an[0], A0.x, Bs);
        ffma2(d[1], A0.y, Bn); ffma2(an[1], A0.y, Bs);
        ffma2(d[2], A1.x, Bn); ffma2(an[2], A1.x, Bs);
        ffma2(d[3], A1.y, Bn); ffma2(an[3], A1.y, Bs);
    }
}

__global__ __launch_bounds__(NTHREADS, 4)
void powerspectrum_kernel(const float* __restrict__ se0,
                          const float* __restrict__ se1,
                          const float* __restrict__ se2,
                          const float* __restrict__ se3,
                          const float* __restrict__ se4,
                          const float* __restrict__ se5,
                          const float* __restrict__ se6,
                          float* __restrict__ out)
{
    const float SQRT2 = 1.4142135623730951f;
    const float INVS2 = 0.70710678118654752f;
    const int PAIR_OFF[NL + 1] = {0, 1, 7, 22, 50, 95, 161, 252};

    extern __shared__ float dyn[];
    float* S = dyn;                        // k-major: S[68*l*l + k*68 + a]
    __shared__ float red[8];
    __shared__ float s_invn;

    const int j    = blockIdx.x;
    const int tid  = threadIdx.x;
    const int lane = tid & 31;
    const int wid  = tid >> 5;

    // ---- stage inputs: float4 gmem reads, k-major transposed smem writes ---
    {
        const float* ses[NL] = {se0, se1, se2, se3, se4, se5, se6};
        #pragma unroll
        for (int l = 0; l < NL; ++l) {
            const int K    = 2 * l + 1;
            const int soff = 68 * l * l;
            const float4* g4 = (const float4*)(ses[l] + (size_t)j * (NA * K));
            const int n4 = NA * K / 4;
            for (int q = tid; q < n4; q += NTHREADS) {
                float4 v = __ldcs(&g4[q]);
                int idx = 4 * q;
                int a = idx / K;
                int k = idx - a * K;
                float vv[4] = {v.x, v.y, v.z, v.w};
                #pragma unroll
                for (int i = 0; i < 4; ++i) {
                    S[soff + k * STRIDE + a] = vv[i];
                    if (++k == K) { k = 0; ++a; }
                }
            }
        }
    }
    __syncthreads();

    // ---- norm via ||S^T S||_F^2: 252 (l, k1<=k2) dot tasks over a=0..63 ----
    float partial = 0.0f;
    if (tid < PAIR_OFF[NL]) {
        int l = 0;
        #pragma unroll
        for (int q = 1; q < NL; ++q)
            if (tid >= PAIR_OFF[q]) l = q;
        int t = tid - PAIR_OFF[l];
        const int K = 2 * l + 1;
        int k1 = 0;
        while (t >= K - k1) { t -= K - k1; ++k1; }
        int k2 = k1 + t;

        const float4* r1 = (const float4*)(S + 68 * l * l + k1 * STRIDE);
        const float4* r2 = (const float4*)(S + 68 * l * l + k2 * STRIDE);
        float dot = 0.0f;
        #pragma unroll
        for (int q = 0; q < NA / 4; ++q) {
            float4 x = r1[q], y = r2[q];
            dot += x.x * y.x + x.y * y.y + x.z * y.z + x.w * y.w;
        }
        float w = (k1 == k2 ? 1.0f : 2.0f) / (float)(2 * l + 1);
        partial = w * dot * dot;
    }
    #pragma unroll
    for (int s = 16; s > 0; s >>= 1)
        partial += __shfl_xor_sync(0xffffffffu, partial, s);
    if (lane == 0) red[wid] = partial;
    __syncthreads();
    if (tid == 0) {
        float tot = 0.0f;
        #pragma unroll
        for (int w = 0; w < 8; ++w) tot += red[w];
        s_invn = 1.0f / fmaxf(sqrtf(tot), 1e-12f);
    }
    __syncthreads();
    const float invn = s_invn;

    float* op = out + (size_t)j * NDIM;

    // ---- strict-triu+diag 8-row slab tasks: 5 packed per l, 35 total -------
    for (int t = wid; t < NWTASK; t += 8) {
        int l   = t / 5;
        int sub = t - l * 5;
        // slabs s: rows [8s,8s+8), col-pairs from 8s; lane width 32-4s.
        // packing: {0}, {1,7}, {2,6}, {3,5}, {4}
        const int sA = sub;
        const int sB = 8 - sub;
        const int nA = 32 - 4 * sub;
        const int nB = (sub == 4) ? 0 : 4 * sub;

        const bool inA    = lane < nA;
        const bool active = lane < nA + nB;
        int rowbase = inA ? 8 * sA : 8 * sB;
        int lanep   = inA ? lane : lane - nA;
        int b       = rowbase + 2 * lanep;
        const bool islast = (lane == nA - 1) || (lane == nA + nB - 1);
        if (!active) { rowbase = 0; b = 0; }

        const float* base = S + 68 * l * l;
        const float* rowA = base + rowbase;
        const float* rowB = base + b;

        u64 d[4], an[4];
        #pragma unroll
        for (int i = 0; i < 4; ++i) { d[i] = 0ull; an[i] = 0ull; }

        switch (l) {
            case 0: slab_gram8< 1>(rowA, rowB, d, an); break;
            case 1: slab_gram8< 3>(rowA, rowB, d, an); break;
            case 2: slab_gram8< 5>(rowA, rowB, d, an); break;
            case 3: slab_gram8< 7>(rowA, rowB, d, an); break;
            case 4: slab_gram8< 9>(rowA, rowB, d, an); break;
            case 5: slab_gram8<11>(rowA, rowB, d, an); break;
            case 6: slab_gram8<13>(rowA, rowB, d, an); break;
        }

        // packed scale by sqrt(2)/sqrt(2l+1)/norm (off-diag scale)
        const float so = __frsqrt_rn((float)(2 * l + 1)) * invn * SQRT2;
        const u64 so2 = dup2(so);
        #pragma unroll
        for (int i = 0; i < 4; ++i) { mul2(d[i], so2); mul2(an[i], so2); }

        float2 ud[4], ua[4];
        #pragma unroll
        for (int i = 0; i < 4; ++i) { ud[i] = unpack2(d[i]); ua[i] = unpack2(an[i]); }

        float* ob = op + l * FEAT_L;

        // rowoff parity vs a (period 4): a%4 in {0,1} -> odd; {2,3} -> even.
        // rowbase % 8 == 0 -> parity compile-time per r. a%4 == r&3.
        #pragma unroll
        for (int r = 0; r < 8; ++r) {
            const int rp = r >> 1;
            // r even: {v0,v1} = {d.lo, a.lo}; r odd: {a.hi, d.hi}
            const float v0 = (r & 1) ? ua[rp].y : ud[rp].x;
            const float v1 = (r & 1) ? ud[rp].y : ua[rp].x;
            const int a      = rowbase + r;
            const int rowoff = 64 + ((a * (127 - a)) >> 1) - a - 1;

            if ((r & 3) == 2) {
                // even rowoff, a even
                if (active) {
                    if (b > a) {
                        *(float2*)(ob + rowoff + b) = make_float2(v0, v1);
                    } else if (b == a) {
                        __stcs(ob + a, v0 * INVS2);            // diag
                        __stcs(ob + rowoff + a + 1, v1);       // element a+1
                    }
                }
            } else if ((r & 3) == 3) {
                // even rowoff, a odd
                if (active) {
                    if (b > a) {
                        *(float2*)(ob + rowoff + b) = make_float2(v0, v1);
                    } else if (b + 1 == a) {
                        __stcs(ob + a, v1 * INVS2);            // diag
                    }
                }
            } else if ((r & 3) == 0) {
                // odd rowoff, a even
                const float nv0 = __shfl_down_sync(0xffffffffu, v0, 1);
                if (active && b >= a) {
                    if (!islast)
                        *(float2*)(ob + rowoff + b + 1) = make_float2(v1, nv0);
                    if (b == a)
                        __stcs(ob + a, v0 * INVS2);            // diag
                    if (islast)
                        __stcs(ob + rowoff + 63, v1);          // tail col 63
                }
            } else {
                // odd rowoff, a odd
                const float nv0 = __shfl_down_sync(0xffffffffu, v0, 1);
                if (active) {
                    if (b > a) {
                        if (!islast)
                            *(float2*)(ob + rowoff + b + 1) = make_float2(v1, nv0);
                        if (islast)
                            __stcs(ob + rowoff + 63, v1);      // tail col 63
                    } else if (b + 1 == a) {
                        __stcs(ob + a, v1 * INVS2);            // diag
                        __stcs(ob + rowoff + a + 1, nv0);      // element a+1
                    }
                }
            }
        }
    }
}

extern "C" void kernel_launch(void* const* d_in, const int* in_sizes, int n_in,
                              void* d_out, int out_size)
{
    const float* se0 = (const float*)d_in[0];
    const float* se1 = (const float*)d_in[1];
    const float* se2 = (const float*)d_in[2];
    const float* se3 = (const float*)d_in[3];
    const float* se4 = (const float*)d_in[4];
    const float* se5 = (const float*)d_in[5];
    const float* se6 = (const float*)d_in[6];
    float* out = (float*)d_out;

    powerspectrum_kernel<<<NJ, NTHREADS, SMEM_BYTES>>>(se0, se1, se2, se3,
                                                       se4, se5, se6, out);
}

// round 12
// speedup vs baseline: 1.0641x; 1.0641x over previous
#include <cuda_runtime.h>

// PowerSpectrum, R12: R10 base (best, 201.5us) + isolated changes:
//  - diagonal-pairing FFMA2 hot loop (13 slots/k vs 15): d[rp]={G[2rp][b],
//    G[2rp+1][b+1]}, an[rp]={G[2rp][b+1],G[2rp+1][b]}; B is a native u64 LDS
//    plus ONE swapped copy (2 MOVs) instead of two dup2s (4 MOVs)
//  - epilogue: EXACT R10 structure + separate diag phase (R11's folding was
//    the suspected regression); only the v0/v1 select source changes
//  - norm prepass FFMA2-ized (16 FFMA2 + horizontal vs 64 FFMA)
//
// Per env j: for l = 0..6, G_l = S_l S_l^T / sqrt(2l+1), S_l: [64, 2l+1].
// features = concat_l [ diag(G_l) (64) ; sqrt(2)*triu(G_l,1) (2016) ] (14560)
// out = features / max(||features||, 1e-12)

#define NJ       8192
#define NA       64
#define NL       7
#define FEAT_L   2080
#define NDIM     14560
#define NTHREADS 256
#define STRIDE   68               // k-row stride in floats
#define S_FLOATS 3332             // 49 * 68
#define SMEM_BYTES (S_FLOATS * 4) // 13328
#define NWTASK   35               // 7 l * 5 packed 8-row slab tasks
#define NDIAG    (NL * NA)        // 448

typedef unsigned long long u64;

__device__ __forceinline__ u64 swap2(u64 v) {
    u64 r;
    asm("{\n\t.reg .f32 lo, hi;\n\t"
        "mov.b64 {lo, hi}, %1;\n\t"
        "mov.b64 %0, {hi, lo};\n\t}"
        : "=l"(r) : "l"(v));
    return r;
}
__device__ __forceinline__ void ffma2(u64& d, u64 a, u64 b) {
    asm("fma.rn.f32x2 %0, %1, %2, %0;" : "+l"(d) : "l"(a), "l"(b));
}
__device__ __forceinline__ void mul2(u64& d, u64 s) {
    asm("mul.rn.f32x2 %0, %0, %1;" : "+l"(d) : "l"(s));
}
__device__ __forceinline__ u64 dup2(float x) {
    u64 r;
    asm("mov.b64 %0, {%1, %1};" : "=l"(r) : "f"(x));
    return r;
}
__device__ __forceinline__ float2 unpack2(u64 v) {
    float lo, hi;
    asm("mov.b64 {%0, %1}, %2;" : "=f"(lo), "=f"(hi) : "l"(v));
    return make_float2(lo, hi);
}

// d[rp] = {G[2rp][b], G[2rp+1][b+1]},  an[rp] = {G[2rp][b+1], G[2rp+1][b]}
template<int K>
__device__ __forceinline__ void slab_gram8(const float* __restrict__ rowA,
                                           const float* __restrict__ rowB,
                                           u64* d, u64* an)
{
    #pragma unroll
    for (int k = 0; k < K; ++k) {
        ulonglong2 A0 = *(const ulonglong2*)(rowA + k * STRIDE);     // rows 0-3
        ulonglong2 A1 = *(const ulonglong2*)(rowA + k * STRIDE + 4); // rows 4-7
        u64 Bn = *(const u64*)(rowB + k * STRIDE);                   // {b, b+1}
        u64 Bs = swap2(Bn);                                          // {b+1, b}
        ffma2(d[0], A0.x, Bn); ffma2(an[0], A0.x, Bs);
        ffma2(d[1], A0.y, Bn); ffma2(an[1], A0.y, Bs);
        ffma2(d[2], A1.x, Bn); ffma2(an[2], A1.x, Bs);
        ffma2(d[3], A1.y, Bn); ffma2(an[3], A1.y, Bs);
    }
}

template<int K>
__device__ __forceinline__ float selfdot(const float* __restrict__ p) {
    float d = 0.0f;
    #pragma unroll
    for (int k = 0; k < K; ++k) { float v = p[k * STRIDE]; d += v * v; }
    return d;
}

__global__ __launch_bounds__(NTHREADS, 4)
void powerspectrum_kernel(const float* __restrict__ se0,
                          const float* __restrict__ se1,
                          const float* __restrict__ se2,
                          const float* __restrict__ se3,
                          const float* __restrict__ se4,
                          const float* __restrict__ se5,
                          const float* __restrict__ se6,
                          float* __restrict__ out)
{
    const float SQRT2 = 1.4142135623730951f;
    const int PAIR_OFF[NL + 1] = {0, 1, 7, 22, 50, 95, 161, 252};

    extern __shared__ float dyn[];
    float* S = dyn;                        // k-major: S[68*l*l + k*68 + a]
    __shared__ float red[8];
    __shared__ float s_invn;

    const int j    = blockIdx.x;
    const int tid  = threadIdx.x;
    const int lane = tid & 31;
    const int wid  = tid >> 5;

    // ---- stage inputs: float4 gmem reads, k-major transposed smem writes ---
    {
        const float* ses[NL] = {se0, se1, se2, se3, se4, se5, se6};
        #pragma unroll
        for (int l = 0; l < NL; ++l) {
            const int K    = 2 * l + 1;
            const int soff = 68 * l * l;
            const float4* g4 = (const float4*)(ses[l] + (size_t)j * (NA * K));
            const int n4 = NA * K / 4;
            for (int q = tid; q < n4; q += NTHREADS) {
                float4 v = __ldcs(&g4[q]);
                int idx = 4 * q;
                int a = idx / K;
                int k = idx - a * K;
                float vv[4] = {v.x, v.y, v.z, v.w};
                #pragma unroll
                for (int i = 0; i < 4; ++i) {
                    S[soff + k * STRIDE + a] = vv[i];
                    if (++k == K) { k = 0; ++a; }
                }
            }
        }
    }
    __syncthreads();

    // ---- norm via ||S^T S||_F^2: 252 (l, k1<=k2) dot tasks over a=0..63 ----
    float partial = 0.0f;
    if (tid < PAIR_OFF[NL]) {
        int l = 0;
        #pragma unroll
        for (int q = 1; q < NL; ++q)
            if (tid >= PAIR_OFF[q]) l = q;
        int t = tid - PAIR_OFF[l];
        const int K = 2 * l + 1;
        int k1 = 0;
        while (t >= K - k1) { t -= K - k1; ++k1; }
        int k2 = k1 + t;

        const ulonglong2* r1 = (const ulonglong2*)(S + 68 * l * l + k1 * STRIDE);
        const ulonglong2* r2 = (const ulonglong2*)(S + 68 * l * l + k2 * STRIDE);
        u64 acc = 0ull;
        #pragma unroll
        for (int q = 0; q < NA / 4; ++q) {
            ulonglong2 x = r1[q], y = r2[q];
            ffma2(acc, x.x, y.x);
            ffma2(acc, x.y, y.y);
        }
        float2 h = unpack2(acc);
        float dot = h.x + h.y;
        float w = (k1 == k2 ? 1.0f : 2.0f) / (float)(2 * l + 1);
        partial = w * dot * dot;
    }
    #pragma unroll
    for (int s = 16; s > 0; s >>= 1)
        partial += __shfl_xor_sync(0xffffffffu, partial, s);
    if (lane == 0) red[wid] = partial;
    __syncthreads();
    if (tid == 0) {
        float tot = 0.0f;
        #pragma unroll
        for (int w = 0; w < 8; ++w) tot += red[w];
        s_invn = 1.0f / fmaxf(sqrtf(tot), 1e-12f);
    }
    __syncthreads();
    const float invn = s_invn;

    float* op = out + (size_t)j * NDIM;

    // ---- diag phase: 448 (l,a) self-dots, coalesced scalar stores ----------
    for (int t = tid; t < NDIAG; t += NTHREADS) {
        int l = t >> 6;
        int a = t & 63;
        const float* p = S + 68 * l * l + a;
        float d;
        switch (l) {
            case 0: d = selfdot< 1>(p); break;
            case 1: d = selfdot< 3>(p); break;
            case 2: d = selfdot< 5>(p); break;
            case 3: d = selfdot< 7>(p); break;
            case 4: d = selfdot< 9>(p); break;
            case 5: d = selfdot<11>(p); break;
            default: d = selfdot<13>(p); break;
        }
        __stcs(op + l * FEAT_L + a,
               d * __frsqrt_rn((float)(2 * l + 1)) * invn);
    }

    // ---- strict-triu 8-row slab tasks: 5 packed per l, 35 total ------------
    for (int t = wid; t < NWTASK; t += 8) {
        int l   = t / 5;
        int sub = t - l * 5;
        // slabs s: rows [8s,8s+8), col-pairs from 8s; lane width 32-4s.
        // packing: {0}, {1,7}, {2,6}, {3,5}, {4}
        const int sA = sub;
        const int sB = 8 - sub;
        const int nA = 32 - 4 * sub;
        const int nB = (sub == 4) ? 0 : 4 * sub;

        const bool inA    = lane < nA;
        const bool active = lane < nA + nB;
        int rowbase = inA ? 8 * sA : 8 * sB;
        int lanep   = inA ? lane : lane - nA;
        int b       = rowbase + 2 * lanep;
        const bool islast = (lane == nA - 1) || (lane == nA + nB - 1);
        if (!active) { rowbase = 0; b = 0; }

        const float* base = S + 68 * l * l;
        const float* rowA = base + rowbase;
        const float* rowB = base + b;

        u64 d[4], an[4];
        #pragma unroll
        for (int i = 0; i < 4; ++i) { d[i] = 0ull; an[i] = 0ull; }

        switch (l) {
            case 0: slab_gram8< 1>(rowA, rowB, d, an); break;
            case 1: slab_gram8< 3>(rowA, rowB, d, an); break;
            case 2: slab_gram8< 5>(rowA, rowB, d, an); break;
            case 3: slab_gram8< 7>(rowA, rowB, d, an); break;
            case 4: slab_gram8< 9>(rowA, rowB, d, an); break;
            case 5: slab_gram8<11>(rowA, rowB, d, an); break;
            case 6: slab_gram8<13>(rowA, rowB, d, an); break;
        }

        // packed scale by sqrt(2)/sqrt(2l+1)/norm
        const float so = __frsqrt_rn((float)(2 * l + 1)) * invn * SQRT2;
        const u64 so2 = dup2(so);
        #pragma unroll
        for (int i = 0; i < 4; ++i) { mul2(d[i], so2); mul2(an[i], so2); }

        float2 ud[4], ua[4];
        #pragma unroll
        for (int i = 0; i < 4; ++i) { ud[i] = unpack2(d[i]); ua[i] = unpack2(an[i]); }

        float* ob = op + l * FEAT_L;

        // rowoff parity pattern vs a (period 4): a%4 = 0,1 -> odd; 2,3 -> even
        // rowbase % 8 == 0, so parity is compile-time per r.  (R10 structure.)
        #pragma unroll
        for (int r = 0; r < 8; ++r) {
            const int rp = r >> 1;
            // pairing select: row even -> (d.x, an.x); row odd -> (an.y, d.y)
            const float v0 = (r & 1) ? ua[rp].y : ud[rp].x;
            const float v1 = (r & 1) ? ud[rp].y : ua[rp].x;
            const int a      = rowbase + r;
            const int rowoff = 64 + ((a * (127 - a)) >> 1) - a - 1;

            if ((r & 3) >= 2) {
                // even rowoff: pair (b, b+1) is 8B-aligned
                if (active) {
                    if (b > a) {
                        *(float2*)(ob + rowoff + b) = make_float2(v0, v1);
                    } else if ((r & 1) == 0 && b == a) {
                        __stcs(ob + rowoff + a + 1, v1);   // element a+1
                    }
                }
            } else {
                // odd rowoff: aligned pairs are (b+1, b+2) = (v1, next v0)
                const float nv0 = __shfl_down_sync(0xffffffffu, v0, 1);
                if (active) {
                    if (b >= a && !islast) {
                        *(float2*)(ob + rowoff + b + 1) = make_float2(v1, nv0);
                    } else if ((r & 1) == 1 && b + 1 == a) {
                        __stcs(ob + rowoff + b + 2, nv0);  // element a+1
                    }
                    if (islast) {
                        __stcs(ob + rowoff + 63, v1);      // tail element 63
                    }
                }
            }
        }
    }
}

extern "C" void kernel_launch(void* const* d_in, const int* in_sizes, int n_in,
                              void* d_out, int out_size)
{
    const float* se0 = (const float*)d_in[0];
    const float* se1 = (const float*)d_in[1];
    const float* se2 = (const float*)d_in[2];
    const float* se3 = (const float*)d_in[3];
    const float* se4 = (const float*)d_in[4];
    const float* se5 = (const float*)d_in[5];
    const float* se6 = (const float*)d_in[6];
    float* out = (float*)d_out;

    powerspectrum_kernel<<<NJ, NTHREADS, SMEM_BYTES>>>(se0, se1, se2, se3,
                                                       se4, se5, se6, out);
}

// round 13
// speedup vs baseline: 1.1847x; 1.1133x over previous
#include <cuda_runtime.h>

// PowerSpectrum, R13: R12 base + two isolated cuts:
//  - branchless destination-major staging: idx = k*64+a -> a=idx&63, k=idx>>6;
//    contiguous STS, scattered-but-L1-resident gmem reads (plain loads, no
//    .cs so L1 retains the <=3.3KB per-(j,l) block)
//  - __launch_bounds__(256,5): regs clamped 63->51, occupancy cap 50%->62.5%
//
// Per env j: for l = 0..6, G_l = S_l S_l^T / sqrt(2l+1), S_l: [64, 2l+1].
// features = concat_l [ diag(G_l) (64) ; sqrt(2)*triu(G_l,1) (2016) ] (14560)
// out = features / max(||features||, 1e-12)

#define NJ       8192
#define NA       64
#define NL       7
#define FEAT_L   2080
#define NDIM     14560
#define NTHREADS 256
#define STRIDE   68               // k-row stride in floats
#define S_FLOATS 3332             // 49 * 68
#define SMEM_BYTES (S_FLOATS * 4) // 13328
#define NWTASK   35               // 7 l * 5 packed 8-row slab tasks
#define NDIAG    (NL * NA)        // 448

typedef unsigned long long u64;

__device__ __forceinline__ u64 swap2(u64 v) {
    u64 r;
    asm("{\n\t.reg .f32 lo, hi;\n\t"
        "mov.b64 {lo, hi}, %1;\n\t"
        "mov.b64 %0, {hi, lo};\n\t}"
        : "=l"(r) : "l"(v));
    return r;
}
__device__ __forceinline__ void ffma2(u64& d, u64 a, u64 b) {
    asm("fma.rn.f32x2 %0, %1, %2, %0;" : "+l"(d) : "l"(a), "l"(b));
}
__device__ __forceinline__ void mul2(u64& d, u64 s) {
    asm("mul.rn.f32x2 %0, %0, %1;" : "+l"(d) : "l"(s));
}
__device__ __forceinline__ u64 dup2(float x) {
    u64 r;
    asm("mov.b64 %0, {%1, %1};" : "=l"(r) : "f"(x));
    return r;
}
__device__ __forceinline__ float2 unpack2(u64 v) {
    float lo, hi;
    asm("mov.b64 {%0, %1}, %2;" : "=f"(lo), "=f"(hi) : "l"(v));
    return make_float2(lo, hi);
}

// d[rp] = {G[2rp][b], G[2rp+1][b+1]},  an[rp] = {G[2rp][b+1], G[2rp+1][b]}
template<int K>
__device__ __forceinline__ void slab_gram8(const float* __restrict__ rowA,
                                           const float* __restrict__ rowB,
                                           u64* d, u64* an)
{
    #pragma unroll
    for (int k = 0; k < K; ++k) {
        ulonglong2 A0 = *(const ulonglong2*)(rowA + k * STRIDE);     // rows 0-3
        ulonglong2 A1 = *(const ulonglong2*)(rowA + k * STRIDE + 4); // rows 4-7
        u64 Bn = *(const u64*)(rowB + k * STRIDE);                   // {b, b+1}
        u64 Bs = swap2(Bn);                                          // {b+1, b}
        ffma2(d[0], A0.x, Bn); ffma2(an[0], A0.x, Bs);
        ffma2(d[1], A0.y, Bn); ffma2(an[1], A0.y, Bs);
        ffma2(d[2], A1.x, Bn); ffma2(an[2], A1.x, Bs);
        ffma2(d[3], A1.y, Bn); ffma2(an[3], A1.y, Bs);
    }
}

template<int K>
__device__ __forceinline__ float selfdot(const float* __restrict__ p) {
    float d = 0.0f;
    #pragma unroll
    for (int k = 0; k < K; ++k) { float v = p[k * STRIDE]; d += v * v; }
    return d;
}

__global__ __launch_bounds__(NTHREADS, 5)
void powerspectrum_kernel(const float* __restrict__ se0,
                          const float* __restrict__ se1,
                          const float* __restrict__ se2,
                          const float* __restrict__ se3,
                          const float* __restrict__ se4,
                          const float* __restrict__ se5,
                          const float* __restrict__ se6,
                          float* __restrict__ out)
{
    const float SQRT2 = 1.4142135623730951f;
    const int PAIR_OFF[NL + 1] = {0, 1, 7, 22, 50, 95, 161, 252};

    extern __shared__ float dyn[];
    float* S = dyn;                        // k-major: S[68*l*l + k*68 + a]
    __shared__ float red[8];
    __shared__ float s_invn;

    const int j    = blockIdx.x;
    const int tid  = threadIdx.x;
    const int lane = tid & 31;
    const int wid  = tid >> 5;

    // ---- stage inputs: destination-major branchless transpose ---------------
    // idx enumerates the k-major destination: a = idx&63, k = idx>>6.
    // STS contiguous/conflict-free; gmem reads scattered but L1-resident
    // (per-(j,l) block <= 3.3KB, swept repeatedly -> hits after first touch).
    {
        const float* ses[NL] = {se0, se1, se2, se3, se4, se5, se6};
        #pragma unroll
        for (int l = 0; l < NL; ++l) {
            const int K    = 2 * l + 1;
            const int soff = 68 * l * l;
            const float* g = ses[l] + (size_t)j * (NA * K);
            const int n = NA * K;
            for (int idx = tid; idx < n; idx += NTHREADS) {
                int a = idx & 63;
                int k = idx >> 6;
                S[soff + k * STRIDE + a] = g[a * K + k];
            }
        }
    }
    __syncthreads();

    // ---- norm via ||S^T S||_F^2: 252 (l, k1<=k2) dot tasks over a=0..63 ----
    float partial = 0.0f;
    if (tid < PAIR_OFF[NL]) {
        int l = 0;
        #pragma unroll
        for (int q = 1; q < NL; ++q)
            if (tid >= PAIR_OFF[q]) l = q;
        int t = tid - PAIR_OFF[l];
        const int K = 2 * l + 1;
        int k1 = 0;
        while (t >= K - k1) { t -= K - k1; ++k1; }
        int k2 = k1 + t;

        const ulonglong2* r1 = (const ulonglong2*)(S + 68 * l * l + k1 * STRIDE);
        const ulonglong2* r2 = (const ulonglong2*)(S + 68 * l * l + k2 * STRIDE);
        u64 acc = 0ull;
        #pragma unroll
        for (int q = 0; q < NA / 4; ++q) {
            ulonglong2 x = r1[q], y = r2[q];
            ffma2(acc, x.x, y.x);
            ffma2(acc, x.y, y.y);
        }
        float2 h = unpack2(acc);
        float dot = h.x + h.y;
        float w = (k1 == k2 ? 1.0f : 2.0f) / (float)(2 * l + 1);
        partial = w * dot * dot;
    }
    #pragma unroll
    for (int s = 16; s > 0; s >>= 1)
        partial += __shfl_xor_sync(0xffffffffu, partial, s);
    if (lane == 0) red[wid] = partial;
    __syncthreads();
    if (tid == 0) {
        float tot = 0.0f;
        #pragma unroll
        for (int w = 0; w < 8; ++w) tot += red[w];
        s_invn = 1.0f / fmaxf(sqrtf(tot), 1e-12f);
    }
    __syncthreads();
    const float invn = s_invn;

    float* op = out + (size_t)j * NDIM;

    // ---- diag phase: 448 (l,a) self-dots, coalesced scalar stores ----------
    for (int t = tid; t < NDIAG; t += NTHREADS) {
        int l = t >> 6;
        int a = t & 63;
        const float* p = S + 68 * l * l + a;
        float d;
        switch (l) {
            case 0: d = selfdot< 1>(p); break;
            case 1: d = selfdot< 3>(p); break;
            case 2: d = selfdot< 5>(p); break;
            case 3: d = selfdot< 7>(p); break;
            case 4: d = selfdot< 9>(p); break;
            case 5: d = selfdot<11>(p); break;
            default: d = selfdot<13>(p); break;
        }
        __stcs(op + l * FEAT_L + a,
               d * __frsqrt_rn((float)(2 * l + 1)) * invn);
    }

    // ---- strict-triu 8-row slab tasks: 5 packed per l, 35 total ------------
    for (int t = wid; t < NWTASK; t += 8) {
        int l   = t / 5;
        int sub = t - l * 5;
        // slabs s: rows [8s,8s+8), col-pairs from 8s; lane width 32-4s.
        // packing: {0}, {1,7}, {2,6}, {3,5}, {4}
        const int sA = sub;
        const int sB = 8 - sub;
        const int nA = 32 - 4 * sub;
        const int nB = (sub == 4) ? 0 : 4 * sub;

        const bool inA    = lane < nA;
        const bool active = lane < nA + nB;
        int rowbase = inA ? 8 * sA : 8 * sB;
        int lanep   = inA ? lane : lane - nA;
        int b       = rowbase + 2 * lanep;
        const bool islast = (lane == nA - 1) || (lane == nA + nB - 1);
        if (!active) { rowbase = 0; b = 0; }

        const float* base = S + 68 * l * l;
        const float* rowA = base + rowbase;
        const float* rowB = base + b;

        u64 d[4], an[4];
        #pragma unroll
        for (int i = 0; i < 4; ++i) { d[i] = 0ull; an[i] = 0ull; }

        switch (l) {
            case 0: slab_gram8< 1>(rowA, rowB, d, an); break;
            case 1: slab_gram8< 3>(rowA, rowB, d, an); break;
            case 2: slab_gram8< 5>(rowA, rowB, d, an); break;
            case 3: slab_gram8< 7>(rowA, rowB, d, an); break;
            case 4: slab_gram8< 9>(rowA, rowB, d, an); break;
            case 5: slab_gram8<11>(rowA, rowB, d, an); break;
            case 6: slab_gram8<13>(rowA, rowB, d, an); break;
        }

        // packed scale by sqrt(2)/sqrt(2l+1)/norm
        const float so = __frsqrt_rn((float)(2 * l + 1)) * invn * SQRT2;
        const u64 so2 = dup2(so);
        #pragma unroll
        for (int i = 0; i < 4; ++i) { mul2(d[i], so2); mul2(an[i], so2); }

        float2 ud[4], ua[4];
        #pragma unroll
        for (int i = 0; i < 4; ++i) { ud[i] = unpack2(d[i]); ua[i] = unpack2(an[i]); }

        float* ob = op + l * FEAT_L;

        // rowoff parity pattern vs a (period 4): a%4 = 0,1 -> odd; 2,3 -> even
        // rowbase % 8 == 0, so parity is compile-time per r.
        #pragma unroll
        for (int r = 0; r < 8; ++r) {
            const int rp = r >> 1;
            // pairing select: row even -> (d.x, an.x); row odd -> (an.y, d.y)
            const float v0 = (r & 1) ? ua[rp].y : ud[rp].x;
            const float v1 = (r & 1) ? ud[rp].y : ua[rp].x;
            const int a      = rowbase + r;
            const int rowoff = 64 + ((a * (127 - a)) >> 1) - a - 1;

            if ((r & 3) >= 2) {
                // even rowoff: pair (b, b+1) is 8B-aligned
                if (active) {
                    if (b > a) {
                        *(float2*)(ob + rowoff + b) = make_float2(v0, v1);
                    } else if ((r & 1) == 0 && b == a) {
                        __stcs(ob + rowoff + a + 1, v1);   // element a+1
                    }
                }
            } else {
                // odd rowoff: aligned pairs are (b+1, b+2) = (v1, next v0)
                const float nv0 = __shfl_down_sync(0xffffffffu, v0, 1);
                if (active) {
                    if (b >= a && !islast) {
                        *(float2*)(ob + rowoff + b + 1) = make_float2(v1, nv0);
                    } else if ((r & 1) == 1 && b + 1 == a) {
                        __stcs(ob + rowoff + b + 2, nv0);  // element a+1
                    }
                    if (islast) {
                        __stcs(ob + rowoff + 63, v1);      // tail element 63
                    }
                }
            }
        }
    }
}

extern "C" void kernel_launch(void* const* d_in, const int* in_sizes, int n_in,
                              void* d_out, int out_size)
{
    const float* se0 = (const float*)d_in[0];
    const float* se1 = (const float*)d_in[1];
    const float* se2 = (const float*)d_in[2];
    const float* se3 = (const float*)d_in[3];
    const float* se4 = (const float*)d_in[4];
    const float* se5 = (const float*)d_in[5];
    const float* se6 = (const float*)d_in[6];
    float* out = (float*)d_out;

    powerspectrum_kernel<<<NJ, NTHREADS, SMEM_BYTES>>>(se0, se1, se2, se3,
                                                       se4, se5, se6, out);
}

// round 15
// speedup vs baseline: 1.2293x; 1.0377x over previous
#include <cuda_runtime.h>

// PowerSpectrum, R14: dumb epilogue.
//  - compute tasks scatter pre-scaled triu values into a packed-triu SMEM
//    buffer (2 predicated STS.32/row; smem has no alignment constraints ->
//    all parity branches / shfl / islast fixups deleted; incremental rowoff)
//  - per-l-pair copy phase streams the buffer to gmem as coalesced float4
//  - phases {0,1},{2,3},{4,5},{6}; F = 16.1KB -> smem 29.5KB, occupancy 5 kept
//
// Per env j: for l = 0..6, G_l = S_l S_l^T / sqrt(2l+1), S_l: [64, 2l+1].
// features = concat_l [ diag(G_l) (64) ; sqrt(2)*triu(G_l,1) (2016) ] (14560)
// out = features / max(||features||, 1e-12)

#define NJ       8192
#define NA       64
#define NL       7
#define FEAT_L   2080
#define TRI_L    2016             // strict-triu floats per l
#define NDIM     14560
#define NTHREADS 256
#define STRIDE   68               // k-row stride in floats
#define S_FLOATS 3332             // 49 * 68
#define F_FLOATS (2 * TRI_L)      // 4032
#define SMEM_BYTES ((S_FLOATS + F_FLOATS) * 4)   // 29456
#define NDIAG    (NL * NA)        // 448

typedef unsigned long long u64;

__device__ __forceinline__ u64 swap2(u64 v) {
    u64 r;
    asm("{\n\t.reg .f32 lo, hi;\n\t"
        "mov.b64 {lo, hi}, %1;\n\t"
        "mov.b64 %0, {hi, lo};\n\t}"
        : "=l"(r) : "l"(v));
    return r;
}
__device__ __forceinline__ void ffma2(u64& d, u64 a, u64 b) {
    asm("fma.rn.f32x2 %0, %1, %2, %0;" : "+l"(d) : "l"(a), "l"(b));
}
__device__ __forceinline__ void mul2(u64& d, u64 s) {
    asm("mul.rn.f32x2 %0, %0, %1;" : "+l"(d) : "l"(s));
}
__device__ __forceinline__ u64 dup2(float x) {
    u64 r;
    asm("mov.b64 %0, {%1, %1};" : "=l"(r) : "f"(x));
    return r;
}
__device__ __forceinline__ float2 unpack2(u64 v) {
    float lo, hi;
    asm("mov.b64 {%0, %1}, %2;" : "=f"(lo), "=f"(hi) : "l"(v));
    return make_float2(lo, hi);
}

// d[rp] = {G[2rp][b], G[2rp+1][b+1]},  an[rp] = {G[2rp][b+1], G[2rp+1][b]}
template<int K>
__device__ __forceinline__ void slab_gram8(const float* __restrict__ rowA,
                                           const float* __restrict__ rowB,
                                           u64* d, u64* an)
{
    #pragma unroll
    for (int k = 0; k < K; ++k) {
        ulonglong2 A0 = *(const ulonglong2*)(rowA + k * STRIDE);     // rows 0-3
        ulonglong2 A1 = *(const ulonglong2*)(rowA + k * STRIDE + 4); // rows 4-7
        u64 Bn = *(const u64*)(rowB + k * STRIDE);                   // {b, b+1}
        u64 Bs = swap2(Bn);                                          // {b+1, b}
        ffma2(d[0], A0.x, Bn); ffma2(an[0], A0.x, Bs);
        ffma2(d[1], A0.y, Bn); ffma2(an[1], A0.y, Bs);
        ffma2(d[2], A1.x, Bn); ffma2(an[2], A1.x, Bs);
        ffma2(d[3], A1.y, Bn); ffma2(an[3], A1.y, Bs);
    }
}

template<int K>
__device__ __forceinline__ float selfdot(const float* __restrict__ p) {
    float d = 0.0f;
    #pragma unroll
    for (int k = 0; k < K; ++k) { float v = p[k * STRIDE]; d += v * v; }
    return d;
}

__global__ __launch_bounds__(NTHREADS, 5)
void powerspectrum_kernel(const float* __restrict__ se0,
                          const float* __restrict__ se1,
                          const float* __restrict__ se2,
                          const float* __restrict__ se3,
                          const float* __restrict__ se4,
                          const float* __restrict__ se5,
                          const float* __restrict__ se6,
                          float* __restrict__ out)
{
    const float SQRT2 = 1.4142135623730951f;
    const int PAIR_OFF[NL + 1] = {0, 1, 7, 22, 50, 95, 161, 252};

    extern __shared__ float dyn[];
    float* S = dyn;                        // k-major: S[68*l*l + k*68 + a]
    float* F = dyn + S_FLOATS;             // [2][2016] packed strict-triu
    __shared__ float red[8];
    __shared__ float s_invn;

    const int j    = blockIdx.x;
    const int tid  = threadIdx.x;
    const int lane = tid & 31;
    const int wid  = tid >> 5;

    // ---- stage inputs: destination-major branchless transpose --------------
    {
        const float* ses[NL] = {se0, se1, se2, se3, se4, se5, se6};
        #pragma unroll
        for (int l = 0; l < NL; ++l) {
            const int K    = 2 * l + 1;
            const int soff = 68 * l * l;
            const float* g = ses[l] + (size_t)j * (NA * K);
            const int n = NA * K;
            for (int idx = tid; idx < n; idx += NTHREADS) {
                int a = idx & 63;
                int k = idx >> 6;
                S[soff + k * STRIDE + a] = g[a * K + k];
            }
        }
    }
    __syncthreads();

    // ---- norm via ||S^T S||_F^2: 252 (l, k1<=k2) dot tasks over a=0..63 ----
    float partial = 0.0f;
    if (tid < PAIR_OFF[NL]) {
        int l = 0;
        #pragma unroll
        for (int q = 1; q < NL; ++q)
            if (tid >= PAIR_OFF[q]) l = q;
        int t = tid - PAIR_OFF[l];
        const int K = 2 * l + 1;
        int k1 = 0;
        while (t >= K - k1) { t -= K - k1; ++k1; }
        int k2 = k1 + t;

        const ulonglong2* r1 = (const ulonglong2*)(S + 68 * l * l + k1 * STRIDE);
        const ulonglong2* r2 = (const ulonglong2*)(S + 68 * l * l + k2 * STRIDE);
        u64 acc = 0ull;
        #pragma unroll
        for (int q = 0; q < NA / 4; ++q) {
            ulonglong2 x = r1[q], y = r2[q];
            ffma2(acc, x.x, y.x);
            ffma2(acc, x.y, y.y);
        }
        float2 h = unpack2(acc);
        float dot = h.x + h.y;
        float w = (k1 == k2 ? 1.0f : 2.0f) / (float)(2 * l + 1);
        partial = w * dot * dot;
    }
    #pragma unroll
    for (int s = 16; s > 0; s >>= 1)
        partial += __shfl_xor_sync(0xffffffffu, partial, s);
    if (lane == 0) red[wid] = partial;
    __syncthreads();
    if (tid == 0) {
        float tot = 0.0f;
        #pragma unroll
        for (int w = 0; w < 8; ++w) tot += red[w];
        s_invn = 1.0f / fmaxf(sqrtf(tot), 1e-12f);
    }
    __syncthreads();
    const float invn = s_invn;

    float* op = out + (size_t)j * NDIM;

    // ---- diag phase: 448 (l,a) self-dots, coalesced scalar gmem stores -----
    for (int t = tid; t < NDIAG; t += NTHREADS) {
        int l = t >> 6;
        int a = t & 63;
        const float* p = S + 68 * l * l + a;
        float d;
        switch (l) {
            case 0: d = selfdot< 1>(p); break;
            case 1: d = selfdot< 3>(p); break;
            case 2: d = selfdot< 5>(p); break;
            case 3: d = selfdot< 7>(p); break;
            case 4: d = selfdot< 9>(p); break;
            case 5: d = selfdot<11>(p); break;
            default: d = selfdot<13>(p); break;
        }
        __stcs(op + l * FEAT_L + a,
               d * __frsqrt_rn((float)(2 * l + 1)) * invn);
    }

    // ---- l-pair phases: compute slabs -> packed-triu smem -> coalesced copy
    #pragma unroll
    for (int p = 0; p < 4; ++p) {
        const int l0    = 2 * p;
        const int ntask = (p < 3) ? 10 : 5;

        // compute: 5 packed 8-row slab tasks per l
        for (int t = wid; t < ntask; t += 8) {
            const int sel = (t >= 5) ? 1 : 0;
            const int l   = l0 + sel;
            const int sub = t - 5 * sel;
            // packing: {0}, {1,7}, {2,6}, {3,5}, {4}; widths 32-4s / 4s lanes
            const int sA = sub;
            const int sB = 8 - sub;
            const int nA = 32 - 4 * sub;
            const int nB = (sub == 4) ? 0 : 4 * sub;

            const bool inA    = lane < nA;
            const bool active = lane < nA + nB;
            int rowbase = inA ? 8 * sA : 8 * sB;
            int lanep   = inA ? lane : lane - nA;
            int b       = rowbase + 2 * lanep;
            if (!active) { rowbase = 0; b = 0; }

            const float* base = S + 68 * l * l;
            const float* rowA = base + rowbase;
            const float* rowB = base + b;

            u64 d[4], an[4];
            #pragma unroll
            for (int i = 0; i < 4; ++i) { d[i] = 0ull; an[i] = 0ull; }

            switch (l) {
                case 0: slab_gram8< 1>(rowA, rowB, d, an); break;
                case 1: slab_gram8< 3>(rowA, rowB, d, an); break;
                case 2: slab_gram8< 5>(rowA, rowB, d, an); break;
                case 3: slab_gram8< 7>(rowA, rowB, d, an); break;
                case 4: slab_gram8< 9>(rowA, rowB, d, an); break;
                case 5: slab_gram8<11>(rowA, rowB, d, an); break;
                case 6: slab_gram8<13>(rowA, rowB, d, an); break;
            }

            // packed scale by sqrt(2)/sqrt(2l+1)/norm
            const float so = __frsqrt_rn((float)(2 * l + 1)) * invn * SQRT2;
            const u64 so2 = dup2(so);
            #pragma unroll
            for (int i = 0; i < 4; ++i) { mul2(d[i], so2); mul2(an[i], so2); }

            float2 ud[4], ua[4];
            #pragma unroll
            for (int i = 0; i < 4; ++i) { ud[i] = unpack2(d[i]); ua[i] = unpack2(an[i]); }

            // scatter into packed-triu smem: fbase[rowoff + b] (origin -64)
            float* fbase = F + sel * TRI_L - 64;
            int a = rowbase;
            int rowoff = 64 + ((a * (127 - a)) >> 1) - a - 1;

            #pragma unroll
            for (int r = 0; r < 8; ++r) {
                const int rp = r >> 1;
                const float v0 = (r & 1) ? ua[rp].y : ud[rp].x;   // (a, b)
                const float v1 = (r & 1) ? ud[rp].y : ua[rp].x;   // (a, b+1)
                if (active && b > a)     fbase[rowoff + b]     = v0;
                if (active && b + 1 > a) fbase[rowoff + b + 1] = v1;
                rowoff += 62 - a;     // rowoff(a+1) - rowoff(a)
                ++a;
            }
        }
        __syncthreads();

        // copy: packed-triu smem -> gmem, fully coalesced float4
        {
            const int nvec = (p < 3) ? (2 * TRI_L / 4) : (TRI_L / 4);  // 1008/504
            const float4* Fv = (const float4*)F;
            for (int i = tid; i < nvec; i += NTHREADS) {
                const int sel = (i >= TRI_L / 4) ? 1 : 0;
                const int ii  = i - sel * (TRI_L / 4);
                float4* dst = (float4*)(op + (l0 + sel) * FEAT_L + 64);
                dst[ii] = Fv[i];
            }
        }
        __syncthreads();
    }
}

extern "C" void kernel_launch(void* const* d_in, const int* in_sizes, int n_in,
                              void* d_out, int out_size)
{
    const float* se0 = (const float*)d_in[0];
    const float* se1 = (const float*)d_in[1];
    const float* se2 = (const float*)d_in[2];
    const float* se3 = (const float*)d_in[3];
    const float* se4 = (const float*)d_in[4];
    const float* se5 = (const float*)d_in[5];
    const float* se6 = (const float*)d_in[6];
    float* out = (float*)d_out;

    powerspectrum_kernel<<<NJ, NTHREADS, SMEM_BYTES>>>(se0, se1, se2, se3,
                                                       se4, se5, se6, out);
}